// round 1
// baseline (speedup 1.0000x reference)
#include <cuda_runtime.h>
#include <cuda_bf16.h>

#define N_NODES  50000
#define N_EDGES  1600000
#define BATCH    4
#define T_STEPS  50
#define DT_CONST 0.02f

#define NCTA     296           // 2 CTAs per SM on 148 SMs (GB300 has 152) -> guaranteed co-resident
#define NTHREADS 512
#define CHUNK    169           // ceil(50000/296); 296*169 = 50024 >= 50000
#define TN       (T_STEPS * N_NODES)

// ---------------- device scratch (static, no allocation) ----------------
__device__ int            g_deg[N_NODES];
__device__ int            g_rowptr[N_NODES + 1];
__device__ int            g_cursor[N_NODES];
__device__ unsigned short g_src[N_EDGES];       // src fits in 16 bits (N < 65536)
__device__ float          g_w[N_EDGES];
__device__ float          g_Vf[N_NODES * 4];    // membrane potential, [n][b]
__device__ float4         g_R[2][N_NODES];      // double-buffered relu(v), [n] x float4(b)
__device__ float          g_alpha[N_NODES];
__device__ int            g_blockSum[NCTA];
__device__ unsigned       g_bar;

// ---------------- grid barrier (monotone counter, reset by init kernel) ----------------
__device__ __forceinline__ void grid_bar(unsigned k) {
    __syncthreads();
    if (threadIdx.x == 0) {
        __threadfence();
        atomicAdd(&g_bar, 1u);
        const unsigned target = k * (unsigned)NCTA;
        while (*(volatile unsigned*)&g_bar < target) { }
    }
    __syncthreads();
}

// ---------------- block-wide inclusive scan (Kogge-Stone in smem) ----------------
__device__ int block_scan_incl(int v) {
    __shared__ int ss[NTHREADS];
    const int tid = threadIdx.x;
    ss[tid] = v;
    __syncthreads();
#pragma unroll
    for (int off = 1; off < NTHREADS; off <<= 1) {
        int t = 0;
        if (tid >= off) t = ss[tid - off];
        __syncthreads();
        if (tid >= off) ss[tid] += t;
        __syncthreads();
    }
    return ss[tid];
}

// ---------------- init kernel: reset per-launch mutable state ----------------
__global__ void init_kernel() {
    int i = blockIdx.x * blockDim.x + threadIdx.x;
    if (i == 0) g_bar = 0u;
    for (int n = i; n < N_NODES; n += gridDim.x * blockDim.x) g_deg[n] = 0;
}

// ---------------- main persistent kernel ----------------
__global__ void __launch_bounds__(NTHREADS, 2) net_kernel(
    const float* __restrict__ x,       // [B, T, N]
    const float* __restrict__ bias,    // [N]
    const float* __restrict__ tconst,  // [N]
    const float* __restrict__ sign,    // [E]
    const float* __restrict__ cnt,     // [E]
    const float* __restrict__ strg,    // [E]
    const int*   __restrict__ src,     // [E]
    const int*   __restrict__ tgt,     // [E]
    float*       __restrict__ out)     // [B, T, N]
{
    const int tid  = threadIdx.x;
    const int bid  = blockIdx.x;
    const int gtid = bid * NTHREADS + tid;
    const int nthr = NCTA * NTHREADS;
    unsigned barK = 0;

    // ---- Pass A: degree histogram over targets ----
    for (int e = gtid; e < N_EDGES; e += nthr)
        atomicAdd(&g_deg[tgt[e]], 1);
    grid_bar(++barK);

    // ---- Pass B1: per-CTA chunk sums ----
    {
        const int n = bid * CHUNK + tid;
        int v = (tid < CHUNK && n < N_NODES) ? g_deg[n] : 0;
        int incl = block_scan_incl(v);
        if (tid == NTHREADS - 1) g_blockSum[bid] = incl;
    }
    grid_bar(++barK);

    // ---- Pass B2: CTA0 exclusive-scans the block sums ----
    if (bid == 0) {
        int v = (tid < NCTA) ? g_blockSum[tid] : 0;
        int incl = block_scan_incl(v);
        if (tid < NCTA) g_blockSum[tid] = incl - v;   // exclusive offset
    }
    grid_bar(++barK);

    // ---- Pass B3: per-chunk exclusive scan -> row_ptr & cursor ----
    {
        const int n = bid * CHUNK + tid;
        int v = (tid < CHUNK && n < N_NODES) ? g_deg[n] : 0;
        int incl = block_scan_incl(v);
        if (tid < CHUNK && n < N_NODES) {
            int rp = g_blockSum[bid] + incl - v;
            g_rowptr[n] = rp;
            g_cursor[n] = rp;
        }
        if (gtid == 0) g_rowptr[N_NODES] = N_EDGES;
    }
    grid_bar(++barK);

    // ---- Pass C: scatter edges into CSR slots, fused weight compute ----
    for (int e = gtid; e < N_EDGES; e += nthr) {
        float w = sign[e] * fmaxf(cnt[e], 0.0f) * fmaxf(strg[e], 0.0f);
        int  t = tgt[e];
        int  p = atomicAdd(&g_cursor[t], 1);
        g_src[p] = (unsigned short)src[e];
        g_w[p]   = w;
    }
    // ---- Pass D: node state init (v = bias, rates0 = relu(bias), alpha) ----
    for (int n = gtid; n < N_NODES; n += nthr) {
        float b   = bias[n];
        float tau = fmaxf(tconst[n], DT_CONST);
        g_alpha[n] = DT_CONST / tau;
        float r = fmaxf(b, 0.0f);
        g_Vf[4 * n + 0] = b; g_Vf[4 * n + 1] = b;
        g_Vf[4 * n + 2] = b; g_Vf[4 * n + 3] = b;
        g_R[0][n] = make_float4(r, r, r, r);
    }
    grid_bar(++barK);

    // ---- Hot loop: 50 steps, warp-per-node gather SpMV + Euler update ----
    const int lane   = tid & 31;
    const int gwarp  = gtid >> 5;
    const int nwarps = nthr >> 5;

    for (int t = 0; t < T_STEPS; t++) {
        const float4* __restrict__ Rc  = g_R[t & 1];
        float*        __restrict__ Rnf = (float*)(g_R[(t + 1) & 1]);
        const float*  __restrict__ xt  = x + t * N_NODES;
        float*        __restrict__ ot  = out + t * N_NODES;

        for (int n = gwarp; n < N_NODES; n += nwarps) {
            const int beg = g_rowptr[n];
            const int end = g_rowptr[n + 1];
            float a0 = 0.f, a1 = 0.f, a2 = 0.f, a3 = 0.f;
            for (int e = beg + lane; e < end; e += 32) {
                float w  = g_w[e];
                int   s  = g_src[e];
                float4 r = __ldcg(&Rc[s]);   // L1-bypass: written cross-SM each step
                a0 = fmaf(w, r.x, a0);
                a1 = fmaf(w, r.y, a1);
                a2 = fmaf(w, r.z, a2);
                a3 = fmaf(w, r.w, a3);
            }
#pragma unroll
            for (int off = 16; off; off >>= 1) {
                a0 += __shfl_xor_sync(0xFFFFFFFFu, a0, off);
                a1 += __shfl_xor_sync(0xFFFFFFFFu, a1, off);
                a2 += __shfl_xor_sync(0xFFFFFFFFu, a2, off);
                a3 += __shfl_xor_sync(0xFFFFFFFFu, a3, off);
            }
            if (lane < 4) {
                float acc = (lane == 0) ? a0 : (lane == 1) ? a1 : (lane == 2) ? a2 : a3;
                float al  = g_alpha[n];
                float b   = bias[n];
                float vv  = g_Vf[4 * n + lane];
                float xv  = xt[lane * TN + n];
                vv += al * (b - vv + acc + xv);
                g_Vf[4 * n + lane] = vv;
                float r = fmaxf(vv, 0.0f);
                Rnf[4 * n + lane] = r;
                ot[lane * TN + n] = r;
            }
        }
        if (t != T_STEPS - 1) grid_bar(++barK);
    }
}

extern "C" void kernel_launch(void* const* d_in, const int* in_sizes, int n_in,
                              void* d_out, int out_size) {
    const float* x      = (const float*)d_in[0];
    const float* bias   = (const float*)d_in[1];
    const float* tconst = (const float*)d_in[2];
    const float* sign   = (const float*)d_in[3];
    const float* cnt    = (const float*)d_in[4];
    const float* strg   = (const float*)d_in[5];
    const int*   src    = (const int*)d_in[6];
    const int*   tgt    = (const int*)d_in[7];
    float*       out    = (float*)d_out;

    init_kernel<<<128, 512>>>();
    net_kernel<<<NCTA, NTHREADS>>>(x, bias, tconst, sign, cnt, strg, src, tgt, out);
}

// round 2
// speedup vs baseline: 1.9825x; 1.9825x over previous
#include <cuda_runtime.h>
#include <cuda_bf16.h>

#define N_NODES  50000
#define N_EDGES  1600000
#define BATCH    4
#define T_STEPS  50
#define DT_CONST 0.02f

#define NCTA     296           // 2 CTAs/SM on 148 SMs -> guaranteed co-resident
#define NTHREADS 512
#define CHUNK    169           // ceil(50000/296)
#define TN       (T_STEPS * N_NODES)
#define QSTRIDE  ((NCTA * NTHREADS) / 4)   // 37888 quads per sweep
#define MAXIT    2                          // ceil(50000 / 37888)

// ---------------- device scratch (static, no allocation) ----------------
__device__ int      g_deg[N_NODES];
__device__ int      g_rowptr[N_NODES + 1];
__device__ int      g_cursor[N_NODES];
__device__ int2     g_ws[N_EDGES];          // {w as bits, src}
__device__ float4   g_R[2][N_NODES];        // double-buffered relu(v), [n] x float4(batch)
__device__ int      g_blockSum[NCTA];
__device__ unsigned g_bar;

// ---------------- grid barrier (monotone counter, reset by init kernel) ----------------
__device__ __forceinline__ void grid_bar(unsigned k) {
    __syncthreads();
    if (threadIdx.x == 0) {
        __threadfence();
        atomicAdd(&g_bar, 1u);
        const unsigned target = k * (unsigned)NCTA;
        while (*(volatile unsigned*)&g_bar < target) { }
    }
    __syncthreads();
}

// ---------------- block-wide inclusive scan (Kogge-Stone in smem) ----------------
__device__ int block_scan_incl(int v) {
    __shared__ int ss[NTHREADS];
    const int tid = threadIdx.x;
    ss[tid] = v;
    __syncthreads();
#pragma unroll
    for (int off = 1; off < NTHREADS; off <<= 1) {
        int t = 0;
        if (tid >= off) t = ss[tid - off];
        __syncthreads();
        if (tid >= off) ss[tid] += t;
        __syncthreads();
    }
    return ss[tid];
}

// ---------------- init kernel: reset per-launch mutable state ----------------
__global__ void init_kernel() {
    int i = blockIdx.x * blockDim.x + threadIdx.x;
    if (i == 0) g_bar = 0u;
    for (int n = i; n < N_NODES; n += gridDim.x * blockDim.x) g_deg[n] = 0;
}

// ---------------- main persistent kernel ----------------
__global__ void __launch_bounds__(NTHREADS, 2) net_kernel(
    const float* __restrict__ x,       // [B, T, N]
    const float* __restrict__ bias,    // [N]
    const float* __restrict__ tconst,  // [N]
    const float* __restrict__ sign,    // [E]
    const float* __restrict__ cnt,     // [E]
    const float* __restrict__ strg,    // [E]
    const int*   __restrict__ src,     // [E]
    const int*   __restrict__ tgt,     // [E]
    float*       __restrict__ out)     // [B, T, N]
{
    const int tid  = threadIdx.x;
    const int bid  = blockIdx.x;
    const int gtid = bid * NTHREADS + tid;
    const int nthr = NCTA * NTHREADS;
    unsigned barK = 0;

    // ---- Pass A: degree histogram over targets ----
    for (int e = gtid; e < N_EDGES; e += nthr)
        atomicAdd(&g_deg[tgt[e]], 1);
    grid_bar(++barK);

    // ---- Pass B1: per-CTA chunk sums ----
    {
        const int n = bid * CHUNK + tid;
        int v = (tid < CHUNK && n < N_NODES) ? g_deg[n] : 0;
        int incl = block_scan_incl(v);
        if (tid == NTHREADS - 1) g_blockSum[bid] = incl;
    }
    grid_bar(++barK);

    // ---- Pass B2: CTA0 exclusive-scans the block sums ----
    if (bid == 0) {
        int v = (tid < NCTA) ? g_blockSum[tid] : 0;
        int incl = block_scan_incl(v);
        if (tid < NCTA) g_blockSum[tid] = incl - v;
    }
    grid_bar(++barK);

    // ---- Pass B3: per-chunk exclusive scan -> row_ptr & cursor ----
    {
        const int n = bid * CHUNK + tid;
        int v = (tid < CHUNK && n < N_NODES) ? g_deg[n] : 0;
        int incl = block_scan_incl(v);
        if (tid < CHUNK && n < N_NODES) {
            int rp = g_blockSum[bid] + incl - v;
            g_rowptr[n] = rp;
            g_cursor[n] = rp;
        }
        if (gtid == 0) g_rowptr[N_NODES] = N_EDGES;
    }
    grid_bar(++barK);

    // ---- Pass C: scatter edges into CSR slots, fused weight compute ----
    for (int e = gtid; e < N_EDGES; e += nthr) {
        float w = sign[e] * fmaxf(cnt[e], 0.0f) * fmaxf(strg[e], 0.0f);
        int  t = tgt[e];
        int  p = atomicAdd(&g_cursor[t], 1);
        g_ws[p] = make_int2(__float_as_int(w), src[e]);
    }

    // ---- Preload per-(row,batch) state into registers; init R[0] ----
    const int q   = tid & 3;          // lane within quad == batch index
    const int qid = gtid >> 2;        // quad id == row id (+ sweeps)
    int   ebeg[MAXIT], eend[MAXIT], xoff[MAXIT], roff[MAXIT];
    float alE[MAXIT], biE[MAXIT], vE[MAXIT];
    int nit = 0;
#pragma unroll
    for (int k = 0; k < MAXIT; k++) {
        int row = qid + k * QSTRIDE;
        if (row < N_NODES) {
            ebeg[k] = g_rowptr[row];
            eend[k] = g_rowptr[row + 1];
            float b   = bias[row];
            float tau = fmaxf(tconst[row], DT_CONST);
            alE[k] = DT_CONST / tau;
            biE[k] = b;
            vE[k]  = b;
            xoff[k] = q * TN + row;
            roff[k] = 4 * row + q;
            ((float*)g_R[0])[roff[k]] = fmaxf(b, 0.0f);
            nit = k + 1;
        } else {
            ebeg[k] = 0; eend[k] = 0; alE[k] = 0.f; biE[k] = 0.f;
            vE[k] = 0.f; xoff[k] = 0; roff[k] = 0;
        }
    }
    grid_bar(++barK);

    // ---- Hot loop: 50 steps, quad-per-row gather SpMV + Euler update ----
    for (int t = 0; t < T_STEPS; t++) {
        const float4* __restrict__ Rc  = g_R[t & 1];
        float*        __restrict__ Rnf = (float*)(g_R[(t + 1) & 1]);
        const float*  __restrict__ xt  = x + t * N_NODES;
        float*        __restrict__ ot  = out + t * N_NODES;

#pragma unroll
        for (int k = 0; k < MAXIT; k++) {
            if (k < nit) {
                unsigned long long a01 = 0ull, a23 = 0ull;   // f32x2 accumulators
                const int e0 = ebeg[k] + q;
                const int e1 = eend[k];
#pragma unroll 4
                for (int e = e0; e < e1; e += 4) {
                    int2 ws = g_ws[e];                       // L1-resident after step 1
                    unsigned long long w2, r01, r23;
                    asm("mov.b64 %0, {%1, %1};" : "=l"(w2) : "r"(ws.x));
                    asm volatile("ld.global.cg.v2.b64 {%0, %1}, [%2];"
                                 : "=l"(r01), "=l"(r23) : "l"(Rc + ws.y));
                    asm("fma.rn.f32x2 %0, %1, %2, %3;" : "=l"(a01) : "l"(w2), "l"(r01), "l"(a01));
                    asm("fma.rn.f32x2 %0, %1, %2, %3;" : "=l"(a23) : "l"(w2), "l"(r23), "l"(a23));
                }
                float f0, f1, f2, f3;
                asm("mov.b64 {%0, %1}, %2;" : "=f"(f0), "=f"(f1) : "l"(a01));
                asm("mov.b64 {%0, %1}, %2;" : "=f"(f2), "=f"(f3) : "l"(a23));
#pragma unroll
                for (int off = 1; off < 4; off <<= 1) {
                    f0 += __shfl_xor_sync(0xFFFFFFFFu, f0, off);
                    f1 += __shfl_xor_sync(0xFFFFFFFFu, f1, off);
                    f2 += __shfl_xor_sync(0xFFFFFFFFu, f2, off);
                    f3 += __shfl_xor_sync(0xFFFFFFFFu, f3, off);
                }
                float acc = (q == 0) ? f0 : (q == 1) ? f1 : (q == 2) ? f2 : f3;
                float xv  = __ldcg(xt + xoff[k]);
                float v   = vE[k];
                v += alE[k] * (biE[k] - v + acc + xv);
                vE[k] = v;
                float r = fmaxf(v, 0.0f);
                Rnf[roff[k]]  = r;
                ot[xoff[k]]   = r;
            }
        }
        if (t != T_STEPS - 1) grid_bar(++barK);
    }
}

extern "C" void kernel_launch(void* const* d_in, const int* in_sizes, int n_in,
                              void* d_out, int out_size) {
    const float* x      = (const float*)d_in[0];
    const float* bias   = (const float*)d_in[1];
    const float* tconst = (const float*)d_in[2];
    const float* sign   = (const float*)d_in[3];
    const float* cnt    = (const float*)d_in[4];
    const float* strg   = (const float*)d_in[5];
    const int*   src    = (const int*)d_in[6];
    const int*   tgt    = (const int*)d_in[7];
    float*       out    = (float*)d_out;

    init_kernel<<<128, 512>>>();
    net_kernel<<<NCTA, NTHREADS>>>(x, bias, tconst, sign, cnt, strg, src, tgt, out);
}